// round 6
// baseline (speedup 1.0000x reference)
#include <cuda_runtime.h>
#include <math.h>
#include <stdint.h>

// Problem dims (fixed by the dataset)
#define NR 4096           // bs*seq = 8*512
#define KC 8192           // codebook size
#define DD 512            // feature dim
#define BSZ 8             // batch size
#define TOT (NR * KC)     // 33554432

// ---------------- scratch (static __device__, allocation-free) ----------------
__device__ float g_logits[(size_t)NR * KC];   // 134 MB
__device__ float g_gum[(size_t)NR * KC];      // 134 MB (gumbel, then overwritten with E)
__device__ float g_zz[NR];
__device__ float g_cc[KC];
__device__ float g_m1[NR], g_iZ1[NR], g_m2[NR], g_iZ2[NR];
__device__ float g_colsum[KC];
__device__ float g_scal[2];  // [0] = sum(p*logp), [1] = sum(diff^2)

// ---------------- zero accumulators (graph replays!) ----------------
__global__ void k_zero() {
    int i = blockIdx.x * blockDim.x + threadIdx.x;
    if (i < KC) g_colsum[i] = 0.f;
    if (i < 2)  g_scal[i]   = 0.f;
}

// ---------------- row squared norms for Z and codebook ----------------
__global__ void k_sumsq(const float* __restrict__ Z, const float* __restrict__ CB) {
    int warp = (blockIdx.x * blockDim.x + threadIdx.x) >> 5;
    int lane = threadIdx.x & 31;
    if (warp >= NR + KC) return;
    const float* p = (warp < NR) ? (Z + (size_t)warp * DD)
                                 : (CB + (size_t)(warp - NR) * DD);
    float s = 0.f;
    #pragma unroll 4
    for (int i = lane; i < DD; i += 32) { float v = p[i]; s += v * v; }
    #pragma unroll
    for (int o = 16; o; o >>= 1) s += __shfl_xor_sync(0xffffffffu, s, o);
    if (lane == 0) { if (warp < NR) g_zz[warp] = s; else g_cc[warp - NR] = s; }
}

// ---------------- Threefry-2x32 gumbel, PARTITIONABLE scheme ----------------
// JAX (threefry_partitionable=True, the modern default):
//   per element i (row-major): counter = (hi32(i), lo32(i)) = (0, i) since
//   TOT < 2^32; 32-bit output = bits0 ^ bits1.
// uniform = bitcast(0x3f800000 | bits>>9) - 1 ; gumbel = -log(-log(u+1e-10)+1e-10)
__global__ void k_gumbel() {
    unsigned i = blockIdx.x * blockDim.x + threadIdx.x;
    unsigned x0 = 0u, x1 = i;
    const unsigned k0 = 0u, k1 = 42u, k2 = 0x1BD11BDAu ^ k0 ^ k1;
    x0 += k0; x1 += k1;
#define TFR(r) { x0 += x1; x1 = __funnelshift_l(x1, x1, r); x1 ^= x0; }
    TFR(13) TFR(15) TFR(26) TFR(6)   x0 += k1; x1 += k2 + 1u;
    TFR(17) TFR(29) TFR(16) TFR(24)  x0 += k2; x1 += k0 + 2u;
    TFR(13) TFR(15) TFR(26) TFR(6)   x0 += k0; x1 += k1 + 3u;
    TFR(17) TFR(29) TFR(16) TFR(24)  x0 += k1; x1 += k2 + 4u;
    TFR(13) TFR(15) TFR(26) TFR(6)   x0 += k2; x1 += k0 + 5u;
#undef TFR
    unsigned bits = x0 ^ x1;
    float u = __uint_as_float(0x3f800000u | (bits >> 9)) - 1.0f;
    g_gum[i] = -logf(-logf(u + 1e-10f) + 1e-10f);
}

// ---------------- GEMM1: logits[n,k] = w*(2*Z.C^T - zz - cc) ----------------
#define BM1 128
#define BN1 128
#define BK1 16
__global__ __launch_bounds__(256) void k_gemm_logits(
    const float* __restrict__ Z, const float* __restrict__ CB,
    const float* __restrict__ varq) {
    __shared__ float As[BK1][BM1 + 1];
    __shared__ float Bs[BK1][BN1];
    const int tid = threadIdx.x;
    const int tx = tid & 15, ty = tid >> 4;
    const int rowBase = blockIdx.y * BM1, colBase = blockIdx.x * BN1;
    const int lr = tid >> 2;     // 0..63
    const int lc = tid & 3;      // 0..3

    float acc[8][8];
    #pragma unroll
    for (int i = 0; i < 8; i++)
        #pragma unroll
        for (int j = 0; j < 8; j++) acc[i][j] = 0.f;

    for (int kk = 0; kk < DD; kk += BK1) {
        #pragma unroll
        for (int rr = 0; rr < BM1; rr += 64) {
            float4 va = *(const float4*)(Z + (size_t)(rowBase + lr + rr) * DD + kk + lc * 4);
            As[lc * 4 + 0][lr + rr] = va.x;
            As[lc * 4 + 1][lr + rr] = va.y;
            As[lc * 4 + 2][lr + rr] = va.z;
            As[lc * 4 + 3][lr + rr] = va.w;
            float4 vb = *(const float4*)(CB + (size_t)(colBase + lr + rr) * DD + kk + lc * 4);
            Bs[lc * 4 + 0][lr + rr] = vb.x;
            Bs[lc * 4 + 1][lr + rr] = vb.y;
            Bs[lc * 4 + 2][lr + rr] = vb.z;
            Bs[lc * 4 + 3][lr + rr] = vb.w;
        }
        __syncthreads();
        #pragma unroll
        for (int p = 0; p < BK1; p++) {
            float a[8], b[8];
            #pragma unroll
            for (int i = 0; i < 8; i++) a[i] = As[p][ty * 8 + i];
            #pragma unroll
            for (int j = 0; j < 8; j++) b[j] = Bs[p][tx * 8 + j];
            #pragma unroll
            for (int i = 0; i < 8; i++)
                #pragma unroll
                for (int j = 0; j < 8; j++) acc[i][j] += a[i] * b[j];
        }
        __syncthreads();
    }

    const float w = 0.5f / fmaxf(varq[0], 1e-10f);
    #pragma unroll
    for (int i = 0; i < 8; i++) {
        int n = rowBase + ty * 8 + i;
        float zzn = g_zz[n];
        float* dst = g_logits + (size_t)n * KC + colBase + tx * 8;
        #pragma unroll
        for (int j = 0; j < 8; j++) {
            int k = colBase + tx * 8 + j;
            dst[j] = w * (2.f * acc[i][j] - zzn - g_cc[k]);
        }
    }
}

// ---------------- per-row softmax stats ----------------
// Track (m, Z, T) with Z = sum e^{l-m}, T = sum e^{l-m} (l-m)  (all O(1) mags)
// row sum p*logp = T/Z - log(Z)
__global__ __launch_bounds__(256) void k_rowstats() {
    const int n = blockIdx.x;
    const float* __restrict__ lrow = g_logits + (size_t)n * KC;
    const float* __restrict__ grow = g_gum + (size_t)n * KC;
    float m1 = -1e30f, Z1 = 0.f, T1 = 0.f, m2 = -1e30f, Z2 = 0.f;
    for (int k = threadIdx.x; k < KC; k += 256) {
        float l = lrow[k];
        float y = 2.0f * (l + grow[k]);   // (logit + g) / 0.5
        if (l > m1) {
            float d = m1 - l;            // <= 0
            float sc = __expf(d);
            T1 = sc * (T1 + d * Z1);
            Z1 *= sc;
            m1 = l;
        }
        float e = __expf(l - m1);
        Z1 += e; T1 += e * (l - m1);
        if (y > m2) { Z2 *= __expf(m2 - y); m2 = y; }
        Z2 += __expf(y - m2);
    }
    __shared__ float sm1[256], sZ1[256], sT1[256], sm2[256], sZ2[256];
    int t = threadIdx.x;
    sm1[t] = m1; sZ1[t] = Z1; sT1[t] = T1; sm2[t] = m2; sZ2[t] = Z2;
    __syncthreads();
    for (int s = 128; s; s >>= 1) {
        if (t < s) {
            int o = t + s;
            float M = fmaxf(sm1[t], sm1[o]);
            float da = sm1[t] - M, db = sm1[o] - M;
            float ea = __expf(da), eb = __expf(db);
            sT1[t] = ea * (sT1[t] + da * sZ1[t]) + eb * (sT1[o] + db * sZ1[o]);
            sZ1[t] = ea * sZ1[t] + eb * sZ1[o];
            sm1[t] = M;
            float M2 = fmaxf(sm2[t], sm2[o]);
            sZ2[t] = sZ2[t] * __expf(sm2[t] - M2) + sZ2[o] * __expf(sm2[o] - M2);
            sm2[t] = M2;
        }
        __syncthreads();
    }
    if (t == 0) {
        float M = sm1[0], Z = sZ1[0], T = sT1[0];
        g_m1[n] = M; g_iZ1[n] = 1.f / Z;
        atomicAdd(&g_scal[0], T / Z - logf(Z));   // sum_k p*logp for this row
        g_m2[n] = sm2[0]; g_iZ2[n] = 1.f / sZ2[0];
    }
}

// ---------------- materialize encodings E in-place over g_gum ----------------
__global__ __launch_bounds__(256) void k_enc() {
    size_t idx = blockIdx.x * (size_t)blockDim.x + threadIdx.x;
    int n = (int)(idx >> 13);   // KC = 8192 = 2^13
    float l = g_logits[idx], g = g_gum[idx];
    g_gum[idx] = __expf(2.f * (l + g) - g_m2[n]) * g_iZ2[n];
}

// ---------------- column sums of probs (avg_probs / perplexity) ----------------
__global__ __launch_bounds__(256) void k_colsum() {
    const int k = blockIdx.x * 256 + threadIdx.x;
    const int n0 = blockIdx.y * (NR / 8);
    float s = 0.f;
    for (int n = n0; n < n0 + NR / 8; n++) {
        s += __expf(g_logits[(size_t)n * KC + k] - g_m1[n]) * g_iZ1[n];
    }
    atomicAdd(&g_colsum[k], s);
}

// ---------------- GEMM2: z_dec = E @ CB  (E precomputed in g_gum) ----------------
#define BM2 64
#define BN2 128
#define BK2 16
__global__ __launch_bounds__(256) void k_gemm_dec(
    const float* __restrict__ CB, float* __restrict__ out) {
    __shared__ float Es[BK2][BM2 + 1];
    __shared__ float Bs[BK2][BN2];
    const int tid = threadIdx.x;
    const int tx = tid & 15, ty = tid >> 4;
    const int rowBase = blockIdx.y * BM2, colBase = blockIdx.x * BN2;
    const int ar = tid >> 2;    // 0..63
    const int ac = tid & 3;     // 0..3
    const int br = tid >> 5;    // 0..7
    const int bc = tid & 31;    // 0..31

    float acc[4][8];
    #pragma unroll
    for (int i = 0; i < 4; i++)
        #pragma unroll
        for (int j = 0; j < 8; j++) acc[i][j] = 0.f;

    for (int kk = 0; kk < KC; kk += BK2) {
        float4 e4 = *(const float4*)(g_gum + (size_t)(rowBase + ar) * KC + kk + ac * 4);
        Es[ac * 4 + 0][ar] = e4.x;
        Es[ac * 4 + 1][ar] = e4.y;
        Es[ac * 4 + 2][ar] = e4.z;
        Es[ac * 4 + 3][ar] = e4.w;
        #pragma unroll
        for (int rr = 0; rr < BK2; rr += 8) {
            float4 vb = *(const float4*)(CB + (size_t)(kk + br + rr) * DD + colBase + bc * 4);
            *(float4*)&Bs[br + rr][bc * 4] = vb;
        }
        __syncthreads();
        #pragma unroll
        for (int p = 0; p < BK2; p++) {
            float a[4], b[8];
            #pragma unroll
            for (int i = 0; i < 4; i++) a[i] = Es[p][ty * 4 + i];
            *(float4*)(b)     = *(const float4*)&Bs[p][tx * 8];
            *(float4*)(b + 4) = *(const float4*)&Bs[p][tx * 8 + 4];
            #pragma unroll
            for (int i = 0; i < 4; i++)
                #pragma unroll
                for (int j = 0; j < 8; j++) acc[i][j] += a[i] * b[j];
        }
        __syncthreads();
    }

    #pragma unroll
    for (int i = 0; i < 4; i++) {
        float* dst = out + (size_t)(rowBase + ty * 4 + i) * DD + colBase + tx * 8;
        #pragma unroll
        for (int j = 0; j < 8; j++) dst[j] = acc[i][j];
    }
}

// ---------------- sum of squared reconstruction error ----------------
__global__ __launch_bounds__(256) void k_diff(const float* __restrict__ Z,
                                              const float* __restrict__ out) {
    __shared__ float sh[256];
    float s = 0.f;
    for (size_t i = blockIdx.x * (size_t)blockDim.x + threadIdx.x;
         i < (size_t)NR * DD; i += (size_t)gridDim.x * blockDim.x) {
        float d = Z[i] - out[i];
        s += d * d;
    }
    sh[threadIdx.x] = s;
    __syncthreads();
    for (int t = 128; t; t >>= 1) {
        if (threadIdx.x < t) sh[threadIdx.x] += sh[threadIdx.x + t];
        __syncthreads();
    }
    if (threadIdx.x == 0) atomicAdd(&g_scal[1], sh[0]);
}

// ---------------- finalize loss + perplexity ----------------
__global__ __launch_bounds__(256) void k_final(const float* __restrict__ varq,
                                               float* __restrict__ out, int out_size) {
    __shared__ float sh[256];
    float s = 0.f;
    for (int k = threadIdx.x; k < KC; k += 256) {
        float a = g_colsum[k] * (1.0f / (float)NR);
        s += a * logf(a + 1e-7f);
    }
    sh[threadIdx.x] = s;
    __syncthreads();
    for (int t = 128; t; t >>= 1) {
        if (threadIdx.x < t) sh[threadIdx.x] += sh[threadIdx.x + t];
        __syncthreads();
    }
    if (threadIdx.x == 0) {
        float w = 0.5f / fmaxf(varq[0], 1e-10f);
        float loss = g_scal[0] / (float)BSZ + w * g_scal[1] / (float)BSZ;
        float perp = expf(-sh[0]);
        if (out_size >= NR * DD + 2) {
            out[(size_t)NR * DD]     = loss;
            out[(size_t)NR * DD + 1] = perp;
        }
    }
}

// ---------------- launch ----------------
extern "C" void kernel_launch(void* const* d_in, const int* in_sizes, int n_in,
                              void* d_out, int out_size) {
    // identify inputs by element count (robust to metadata ordering)
    const float *Z = 0, *varq = 0, *CB = 0;
    for (int i = 0; i < n_in; i++) {
        if (in_sizes[i] == 1)            varq = (const float*)d_in[i];
        else if (in_sizes[i] == NR * DD) Z    = (const float*)d_in[i];
        else if (in_sizes[i] == KC * DD) CB   = (const float*)d_in[i];
    }
    float* out = (float*)d_out;

    k_zero<<<(KC + 255) / 256, 256>>>();
    k_sumsq<<<((NR + KC) * 32 + 255) / 256, 256>>>(Z, CB);
    k_gumbel<<<TOT / 256, 256>>>();
    k_gemm_logits<<<dim3(KC / BN1, NR / BM1), 256>>>(Z, CB, varq);
    k_rowstats<<<NR, 256>>>();
    k_enc<<<TOT / 256, 256>>>();
    k_colsum<<<dim3(KC / 256, 8), 256>>>();
    k_gemm_dec<<<dim3(DD / BN2, NR / BM2), 256>>>(CB, out);
    k_diff<<<1024, 256>>>(Z, out);
    k_final<<<1, 256>>>(varq, out, out_size);
}

// round 7
// speedup vs baseline: 1.3743x; 1.3743x over previous
#include <cuda_runtime.h>
#include <math.h>
#include <stdint.h>

// Problem dims (fixed by the dataset)
#define NR 4096           // bs*seq = 8*512
#define KC 8192           // codebook size
#define DD 512            // feature dim
#define BSZ 8             // batch size
#define TOT (NR * KC)     // 33554432

// ---------------- scratch (static __device__, allocation-free) ----------------
__device__ float g_logits[(size_t)NR * KC];   // 134 MB
__device__ float g_gum[(size_t)NR * KC];      // 134 MB (gumbel, then overwritten with E)
__device__ float g_zz[NR];
__device__ float g_cc[KC];
__device__ float g_m1[NR], g_iZ1[NR];
__device__ float g_colsum[KC];
__device__ float g_scal[2];  // [0] = sum(p*logp), [1] = sum(diff^2)

// ---------------- zero accumulators (graph replays!) ----------------
__global__ void k_zero() {
    int i = blockIdx.x * blockDim.x + threadIdx.x;
    if (i < KC) g_colsum[i] = 0.f;
    if (i < 2)  g_scal[i]   = 0.f;
}

// ---------------- row squared norms for Z and codebook ----------------
__global__ void k_sumsq(const float* __restrict__ Z, const float* __restrict__ CB) {
    int warp = (blockIdx.x * blockDim.x + threadIdx.x) >> 5;
    int lane = threadIdx.x & 31;
    if (warp >= NR + KC) return;
    const float* p = (warp < NR) ? (Z + (size_t)warp * DD)
                                 : (CB + (size_t)(warp - NR) * DD);
    float s = 0.f;
    #pragma unroll 4
    for (int i = lane; i < DD; i += 32) { float v = p[i]; s += v * v; }
    #pragma unroll
    for (int o = 16; o; o >>= 1) s += __shfl_xor_sync(0xffffffffu, s, o);
    if (lane == 0) { if (warp < NR) g_zz[warp] = s; else g_cc[warp - NR] = s; }
}

// ---------------- Threefry-2x32 gumbel, PARTITIONABLE scheme ----------------
// out[i] = x0 ^ x1 with counter (0, i); key (0, 42).
// uniform = bitcast(0x3f800000 | bits>>9) - 1
// gumbel = -log(-log(u+1e-10)+1e-10); logs via MUFU except u->1 (series).
__global__ void k_gumbel() {
    unsigned i = blockIdx.x * blockDim.x + threadIdx.x;
    unsigned x0 = 0u, x1 = i;
    const unsigned k0 = 0u, k1 = 42u, k2 = 0x1BD11BDAu ^ k0 ^ k1;
    x0 += k0; x1 += k1;
#define TFR(r) { x0 += x1; x1 = __funnelshift_l(x1, x1, r); x1 ^= x0; }
    TFR(13) TFR(15) TFR(26) TFR(6)   x0 += k1; x1 += k2 + 1u;
    TFR(17) TFR(29) TFR(16) TFR(24)  x0 += k2; x1 += k0 + 2u;
    TFR(13) TFR(15) TFR(26) TFR(6)   x0 += k0; x1 += k1 + 3u;
    TFR(17) TFR(29) TFR(16) TFR(24)  x0 += k1; x1 += k2 + 4u;
    TFR(13) TFR(15) TFR(26) TFR(6)   x0 += k2; x1 += k0 + 5u;
#undef TFR
    unsigned bits = x0 ^ x1;
    float u = __uint_as_float(0x3f800000u | (bits >> 9)) - 1.0f;
    // inner: t = -log(u + 1e-10)
    float x = u - 1.0f;                       // exact (Sterbenz) for u in [0.5,1]
    // series for ln(1+x)/x, |x| <= 0.1: rel err ~1e-8
    float pl = 1.f + x * (-0.5f + x * (0.33333334f + x * (-0.25f +
               x * (0.2f + x * (-0.16666667f + x * 0.14285715f)))));
    float ts = -x * pl;                       // accurate -ln(u) for u near 1
    float tm = -__logf(u + 1e-10f);           // MUFU path elsewhere
    float t = (u > 0.9f) ? ts : tm;
    g_gum[i] = -__logf(t + 1e-10f);
}

// ---------------- GEMM1: logits[n,k] = w*(2*Z.C^T - zz - cc) ----------------
// 128x128x16 tile, double-buffered smem, 8x8 micro-tile, 256 threads.
#define BM1 128
#define BN1 128
#define BK1 16
#define LDT (BM1 + 8)   // 136 floats: rows 16B-aligned, conflict-free STS
__global__ __launch_bounds__(256) void k_gemm_logits(
    const float* __restrict__ Z, const float* __restrict__ CB,
    const float* __restrict__ varq) {
    __shared__ float As[2][BK1][LDT];
    __shared__ float Bs[2][BK1][LDT];
    const int tid = threadIdx.x;
    const int tx = tid & 15, ty = tid >> 4;
    const int rowBase = blockIdx.y * BM1, colBase = blockIdx.x * BN1;
    const int lr = tid >> 2;     // 0..63
    const int lc = tid & 3;      // 0..3

    const float* Ap = Z  + (size_t)(rowBase + lr) * DD + lc * 4;
    const float* Bp = CB + (size_t)(colBase + lr) * DD + lc * 4;

    float4 va0 = *(const float4*)(Ap);
    float4 va1 = *(const float4*)(Ap + 64 * DD);
    float4 vb0 = *(const float4*)(Bp);
    float4 vb1 = *(const float4*)(Bp + 64 * DD);

    As[0][lc*4+0][lr]    = va0.x; As[0][lc*4+1][lr]    = va0.y;
    As[0][lc*4+2][lr]    = va0.z; As[0][lc*4+3][lr]    = va0.w;
    As[0][lc*4+0][lr+64] = va1.x; As[0][lc*4+1][lr+64] = va1.y;
    As[0][lc*4+2][lr+64] = va1.z; As[0][lc*4+3][lr+64] = va1.w;
    Bs[0][lc*4+0][lr]    = vb0.x; Bs[0][lc*4+1][lr]    = vb0.y;
    Bs[0][lc*4+2][lr]    = vb0.z; Bs[0][lc*4+3][lr]    = vb0.w;
    Bs[0][lc*4+0][lr+64] = vb1.x; Bs[0][lc*4+1][lr+64] = vb1.y;
    Bs[0][lc*4+2][lr+64] = vb1.z; Bs[0][lc*4+3][lr+64] = vb1.w;
    __syncthreads();

    float acc[8][8];
    #pragma unroll
    for (int i = 0; i < 8; i++)
        #pragma unroll
        for (int j = 0; j < 8; j++) acc[i][j] = 0.f;

    const int NIT = DD / BK1;   // 32
    for (int kk = 0; kk < NIT; kk++) {
        const int cur = kk & 1, nxt = cur ^ 1;
        if (kk + 1 < NIT) {
            const float* Ap2 = Ap + (kk + 1) * BK1;
            const float* Bp2 = Bp + (kk + 1) * BK1;
            va0 = *(const float4*)(Ap2);
            va1 = *(const float4*)(Ap2 + 64 * DD);
            vb0 = *(const float4*)(Bp2);
            vb1 = *(const float4*)(Bp2 + 64 * DD);
        }
        #pragma unroll
        for (int p = 0; p < BK1; p++) {
            float a[8], b[8];
            *(float4*)(a)     = *(const float4*)&As[cur][p][ty * 8];
            *(float4*)(a + 4) = *(const float4*)&As[cur][p][ty * 8 + 4];
            *(float4*)(b)     = *(const float4*)&Bs[cur][p][tx * 8];
            *(float4*)(b + 4) = *(const float4*)&Bs[cur][p][tx * 8 + 4];
            #pragma unroll
            for (int i = 0; i < 8; i++)
                #pragma unroll
                for (int j = 0; j < 8; j++) acc[i][j] += a[i] * b[j];
        }
        if (kk + 1 < NIT) {
            As[nxt][lc*4+0][lr]    = va0.x; As[nxt][lc*4+1][lr]    = va0.y;
            As[nxt][lc*4+2][lr]    = va0.z; As[nxt][lc*4+3][lr]    = va0.w;
            As[nxt][lc*4+0][lr+64] = va1.x; As[nxt][lc*4+1][lr+64] = va1.y;
            As[nxt][lc*4+2][lr+64] = va1.z; As[nxt][lc*4+3][lr+64] = va1.w;
            Bs[nxt][lc*4+0][lr]    = vb0.x; Bs[nxt][lc*4+1][lr]    = vb0.y;
            Bs[nxt][lc*4+2][lr]    = vb0.z; Bs[nxt][lc*4+3][lr]    = vb0.w;
            Bs[nxt][lc*4+0][lr+64] = vb1.x; Bs[nxt][lc*4+1][lr+64] = vb1.y;
            Bs[nxt][lc*4+2][lr+64] = vb1.z; Bs[nxt][lc*4+3][lr+64] = vb1.w;
        }
        __syncthreads();
    }

    const float w = 0.5f / fmaxf(varq[0], 1e-10f);
    #pragma unroll
    for (int i = 0; i < 8; i++) {
        int n = rowBase + ty * 8 + i;
        float zzn = g_zz[n];
        float* dst = g_logits + (size_t)n * KC + colBase + tx * 8;
        #pragma unroll
        for (int j = 0; j < 8; j++) {
            int k = colBase + tx * 8 + j;
            dst[j] = w * (2.f * acc[i][j] - zzn - g_cc[k]);
        }
    }
}

// ---------------- per-row softmax stats + E materialization ----------------
// Track (m, Z, T): Z = sum e^{l-m}, T = sum e^{l-m}(l-m); row p*logp = T/Z - logZ.
// Phase 2 writes encodings E = softmax((l+g)/T) in place over g_gum.
__global__ __launch_bounds__(256) void k_rowstats() {
    const int n = blockIdx.x;
    float* __restrict__ lrow = g_logits + (size_t)n * KC;
    float* __restrict__ grow = g_gum + (size_t)n * KC;
    float m1 = -1e30f, Z1 = 0.f, T1 = 0.f, m2 = -1e30f, Z2 = 0.f;
    for (int k = threadIdx.x * 4; k < KC; k += 1024) {
        float4 l4 = *(const float4*)(lrow + k);
        float4 g4 = *(const float4*)(grow + k);
        #pragma unroll
        for (int q = 0; q < 4; q++) {
            float l = (q == 0) ? l4.x : (q == 1) ? l4.y : (q == 2) ? l4.z : l4.w;
            float g = (q == 0) ? g4.x : (q == 1) ? g4.y : (q == 2) ? g4.z : g4.w;
            float y = 2.0f * (l + g);
            if (l > m1) {
                float d = m1 - l;
                float sc = __expf(d);
                T1 = sc * (T1 + d * Z1);
                Z1 *= sc;
                m1 = l;
            }
            float e = __expf(l - m1);
            Z1 += e; T1 += e * (l - m1);
            if (y > m2) { Z2 *= __expf(m2 - y); m2 = y; }
            Z2 += __expf(y - m2);
        }
    }
    __shared__ float sm1[256], sZ1[256], sT1[256], sm2[256], sZ2[256];
    __shared__ float s_fin[2];
    int t = threadIdx.x;
    sm1[t] = m1; sZ1[t] = Z1; sT1[t] = T1; sm2[t] = m2; sZ2[t] = Z2;
    __syncthreads();
    for (int s = 128; s; s >>= 1) {
        if (t < s) {
            int o = t + s;
            float M = fmaxf(sm1[t], sm1[o]);
            float da = sm1[t] - M, db = sm1[o] - M;
            float ea = __expf(da), eb = __expf(db);
            sT1[t] = ea * (sT1[t] + da * sZ1[t]) + eb * (sT1[o] + db * sZ1[o]);
            sZ1[t] = ea * sZ1[t] + eb * sZ1[o];
            sm1[t] = M;
            float M2 = fmaxf(sm2[t], sm2[o]);
            sZ2[t] = sZ2[t] * __expf(sm2[t] - M2) + sZ2[o] * __expf(sm2[o] - M2);
            sm2[t] = M2;
        }
        __syncthreads();
    }
    if (t == 0) {
        float M = sm1[0], Z = sZ1[0], T = sT1[0];
        g_m1[n] = M; g_iZ1[n] = 1.f / Z;
        atomicAdd(&g_scal[0], T / Z - logf(Z));
        s_fin[0] = sm2[0]; s_fin[1] = 1.f / sZ2[0];
    }
    __syncthreads();
    const float m2v = s_fin[0], iZ2 = s_fin[1];
    for (int k = threadIdx.x * 4; k < KC; k += 1024) {
        float4 l4 = *(const float4*)(lrow + k);
        float4 g4 = *(const float4*)(grow + k);
        float4 E;
        E.x = __expf(2.f * (l4.x + g4.x) - m2v) * iZ2;
        E.y = __expf(2.f * (l4.y + g4.y) - m2v) * iZ2;
        E.z = __expf(2.f * (l4.z + g4.z) - m2v) * iZ2;
        E.w = __expf(2.f * (l4.w + g4.w) - m2v) * iZ2;
        *(float4*)(grow + k) = E;
    }
}

// ---------------- column sums of probs (avg_probs / perplexity) ----------------
__global__ __launch_bounds__(256) void k_colsum() {
    const int k = blockIdx.x * 256 + threadIdx.x;
    const int n0 = blockIdx.y * (NR / 8);
    float s = 0.f;
    for (int n = n0; n < n0 + NR / 8; n++) {
        s += __expf(g_logits[(size_t)n * KC + k] - g_m1[n]) * g_iZ1[n];
    }
    atomicAdd(&g_colsum[k], s);
}

// ---------------- GEMM2: z_dec = E @ CB  (E in g_gum) ----------------
// 128x64x16 tile, double-buffered, 8x4 micro-tile, 256 threads.
#define BM2 128
#define BN2 64
#define BK2 16
__global__ __launch_bounds__(256, 3) void k_gemm_dec(
    const float* __restrict__ CB, float* __restrict__ out) {
    __shared__ float Es[2][BK2][LDT];
    __shared__ float Bs[2][BK2][BN2];
    const int tid = threadIdx.x;
    const int tx = tid & 15, ty = tid >> 4;
    const int rowBase = blockIdx.y * BM2, colBase = blockIdx.x * BN2;
    const int lr = tid >> 2;    // 0..63
    const int lc = tid & 3;     // 0..3
    const int kr = tid >> 4;    // 0..15  (B loader row)
    const int nc = (tid & 15) * 4;  // B loader col

    const float* Ep = g_gum + (size_t)(rowBase + lr) * KC + lc * 4;
    const float* Bp = CB + (size_t)kr * DD + colBase + nc;

    float4 ve0 = *(const float4*)(Ep);
    float4 ve1 = *(const float4*)(Ep + 64 * KC);
    float4 vb  = *(const float4*)(Bp);

    Es[0][lc*4+0][lr]    = ve0.x; Es[0][lc*4+1][lr]    = ve0.y;
    Es[0][lc*4+2][lr]    = ve0.z; Es[0][lc*4+3][lr]    = ve0.w;
    Es[0][lc*4+0][lr+64] = ve1.x; Es[0][lc*4+1][lr+64] = ve1.y;
    Es[0][lc*4+2][lr+64] = ve1.z; Es[0][lc*4+3][lr+64] = ve1.w;
    *(float4*)&Bs[0][kr][nc] = vb;
    __syncthreads();

    float acc[8][4];
    #pragma unroll
    for (int i = 0; i < 8; i++)
        #pragma unroll
        for (int j = 0; j < 4; j++) acc[i][j] = 0.f;

    const int NIT = KC / BK2;   // 512
    for (int kk = 0; kk < NIT; kk++) {
        const int cur = kk & 1, nxt = cur ^ 1;
        if (kk + 1 < NIT) {
            ve0 = *(const float4*)(Ep + (kk + 1) * BK2);
            ve1 = *(const float4*)(Ep + (kk + 1) * BK2 + 64 * KC);
            vb  = *(const float4*)(Bp + (size_t)(kk + 1) * BK2 * DD);
        }
        #pragma unroll
        for (int p = 0; p < BK2; p++) {
            float a[8], b[4];
            *(float4*)(a)     = *(const float4*)&Es[cur][p][ty * 8];
            *(float4*)(a + 4) = *(const float4*)&Es[cur][p][ty * 8 + 4];
            *(float4*)(b)     = *(const float4*)&Bs[cur][p][tx * 4];
            #pragma unroll
            for (int i = 0; i < 8; i++)
                #pragma unroll
                for (int j = 0; j < 4; j++) acc[i][j] += a[i] * b[j];
        }
        if (kk + 1 < NIT) {
            Es[nxt][lc*4+0][lr]    = ve0.x; Es[nxt][lc*4+1][lr]    = ve0.y;
            Es[nxt][lc*4+2][lr]    = ve0.z; Es[nxt][lc*4+3][lr]    = ve0.w;
            Es[nxt][lc*4+0][lr+64] = ve1.x; Es[nxt][lc*4+1][lr+64] = ve1.y;
            Es[nxt][lc*4+2][lr+64] = ve1.z; Es[nxt][lc*4+3][lr+64] = ve1.w;
            *(float4*)&Bs[nxt][kr][nc] = vb;
        }
        __syncthreads();
    }

    #pragma unroll
    for (int i = 0; i < 8; i++) {
        float* dst = out + (size_t)(rowBase + ty * 8 + i) * DD + colBase + tx * 4;
        float4 v; v.x = acc[i][0]; v.y = acc[i][1]; v.z = acc[i][2]; v.w = acc[i][3];
        *(float4*)dst = v;
    }
}

// ---------------- sum of squared reconstruction error ----------------
__global__ __launch_bounds__(256) void k_diff(const float* __restrict__ Z,
                                              const float* __restrict__ out) {
    __shared__ float sh[256];
    float s = 0.f;
    for (size_t i = blockIdx.x * (size_t)blockDim.x + threadIdx.x;
         i < (size_t)NR * DD; i += (size_t)gridDim.x * blockDim.x) {
        float d = Z[i] - out[i];
        s += d * d;
    }
    sh[threadIdx.x] = s;
    __syncthreads();
    for (int t = 128; t; t >>= 1) {
        if (threadIdx.x < t) sh[threadIdx.x] += sh[threadIdx.x + t];
        __syncthreads();
    }
    if (threadIdx.x == 0) atomicAdd(&g_scal[1], sh[0]);
}

// ---------------- finalize loss + perplexity ----------------
__global__ __launch_bounds__(256) void k_final(const float* __restrict__ varq,
                                               float* __restrict__ out, int out_size) {
    __shared__ float sh[256];
    float s = 0.f;
    for (int k = threadIdx.x; k < KC; k += 256) {
        float a = g_colsum[k] * (1.0f / (float)NR);
        s += a * logf(a + 1e-7f);
    }
    sh[threadIdx.x] = s;
    __syncthreads();
    for (int t = 128; t; t >>= 1) {
        if (threadIdx.x < t) sh[threadIdx.x] += sh[threadIdx.x + t];
        __syncthreads();
    }
    if (threadIdx.x == 0) {
        float w = 0.5f / fmaxf(varq[0], 1e-10f);
        float loss = g_scal[0] / (float)BSZ + w * g_scal[1] / (float)BSZ;
        float perp = expf(-sh[0]);
        if (out_size >= NR * DD + 2) {
            out[(size_t)NR * DD]     = loss;
            out[(size_t)NR * DD + 1] = perp;
        }
    }
}

// ---------------- launch ----------------
extern "C" void kernel_launch(void* const* d_in, const int* in_sizes, int n_in,
                              void* d_out, int out_size) {
    // identify inputs by element count (robust to metadata ordering)
    const float *Z = 0, *varq = 0, *CB = 0;
    for (int i = 0; i < n_in; i++) {
        if (in_sizes[i] == 1)            varq = (const float*)d_in[i];
        else if (in_sizes[i] == NR * DD) Z    = (const float*)d_in[i];
        else if (in_sizes[i] == KC * DD) CB   = (const float*)d_in[i];
    }
    float* out = (float*)d_out;

    k_zero<<<(KC + 255) / 256, 256>>>();
    k_sumsq<<<((NR + KC) * 32 + 255) / 256, 256>>>(Z, CB);
    k_gumbel<<<TOT / 256, 256>>>();
    k_gemm_logits<<<dim3(KC / BN1, NR / BM1), 256>>>(Z, CB, varq);
    k_rowstats<<<NR, 256>>>();   // also writes E over g_gum
    k_colsum<<<dim3(KC / 256, 8), 256>>>();
    k_gemm_dec<<<dim3(DD / BN2, NR / BM2), 256>>>(CB, out);
    k_diff<<<1024, 256>>>(Z, out);
    k_final<<<1, 256>>>(varq, out, out_size);
}

// round 9
// speedup vs baseline: 2.5628x; 1.8648x over previous
#include <cuda_runtime.h>
#include <math.h>
#include <stdint.h>

// Problem dims (fixed by the dataset)
#define NR 4096           // bs*seq
#define KC 8192           // codebook size
#define DD 512            // feature dim
#define BSZ 8
#define TOT (NR * KC)

// ---------------- scratch (static __device__, allocation-free) ----------------
__device__ float g_logits[(size_t)NR * KC];   // 134 MB
__device__ float g_zz[NR];
__device__ float g_cc[KC];
__device__ float g_colsum[KC];
__device__ float g_scal[2];  // [0] = sum(p*logp), [1] = sum(diff^2)

// ---------------- zero accumulators (graph replays!) ----------------
__global__ void k_zero() {
    int i = blockIdx.x * blockDim.x + threadIdx.x;
    if (i < KC) g_colsum[i] = 0.f;
    if (i < 2)  g_scal[i]   = 0.f;
}

// ---------------- row squared norms ----------------
__global__ void k_sumsq(const float* __restrict__ Z, const float* __restrict__ CB) {
    int warp = (blockIdx.x * blockDim.x + threadIdx.x) >> 5;
    int lane = threadIdx.x & 31;
    if (warp >= NR + KC) return;
    const float* p = (warp < NR) ? (Z + (size_t)warp * DD)
                                 : (CB + (size_t)(warp - NR) * DD);
    float s = 0.f;
    #pragma unroll 4
    for (int i = lane; i < DD; i += 32) { float v = p[i]; s += v * v; }
    #pragma unroll
    for (int o = 16; o; o >>= 1) s += __shfl_xor_sync(0xffffffffu, s, o);
    if (lane == 0) { if (warp < NR) g_zz[warp] = s; else g_cc[warp - NR] = s; }
}

// ---------------- Threefry-2x32 gumbel (partitionable scheme), pure fn of i ----
// counter (0, i), key (0, 42); 32-bit output = x0 ^ x1.
// uniform = bitcast(0x3f800000 | bits>>9) - 1
// gumbel = -log(-log(u+1e-10)+1e-10); MUFU logs except u->1 (accurate series).
__device__ __forceinline__ float gumbel_of(unsigned i) {
    unsigned x0 = 0u, x1 = i;
    const unsigned k0 = 0u, k1 = 42u, k2 = 0x1BD11BDAu ^ k0 ^ k1;
    x0 += k0; x1 += k1;
#define TFR(r) { x0 += x1; x1 = __funnelshift_l(x1, x1, r); x1 ^= x0; }
    TFR(13) TFR(15) TFR(26) TFR(6)   x0 += k1; x1 += k2 + 1u;
    TFR(17) TFR(29) TFR(16) TFR(24)  x0 += k2; x1 += k0 + 2u;
    TFR(13) TFR(15) TFR(26) TFR(6)   x0 += k0; x1 += k1 + 3u;
    TFR(17) TFR(29) TFR(16) TFR(24)  x0 += k1; x1 += k2 + 4u;
    TFR(13) TFR(15) TFR(26) TFR(6)   x0 += k2; x1 += k0 + 5u;
#undef TFR
    unsigned bits = x0 ^ x1;
    float u = __uint_as_float(0x3f800000u | (bits >> 9)) - 1.0f;
    float x = u - 1.0f;                       // exact (Sterbenz) for u in [0.5,1]
    float pl = 1.f + x * (-0.5f + x * (0.33333334f + x * (-0.25f +
               x * (0.2f + x * (-0.16666667f + x * 0.14285715f)))));
    float ts = -x * pl;                       // accurate -ln(u), u near 1
    float tm = -__logf(u + 1e-10f);
    float t = (u > 0.9f) ? ts : tm;
    return -__logf(t + 1e-10f);
}

// ---------------- GEMM1: logits[n,k] = w*(2*Z.C^T - zz - cc) ----------------
// 128x128x16 tile, double-buffered smem, 8x8 micro-tile, 256 threads. (R7-proven)
#define BM1 128
#define BN1 128
#define BK1 16
#define LDT (BM1 + 8)
__global__ __launch_bounds__(256) void k_gemm_logits(
    const float* __restrict__ Z, const float* __restrict__ CB,
    const float* __restrict__ varq) {
    __shared__ float As[2][BK1][LDT];
    __shared__ float Bs[2][BK1][LDT];
    const int tid = threadIdx.x;
    const int tx = tid & 15, ty = tid >> 4;
    const int rowBase = blockIdx.y * BM1, colBase = blockIdx.x * BN1;
    const int lr = tid >> 2;     // 0..63
    const int lc = tid & 3;      // 0..3

    const float* Ap = Z  + (size_t)(rowBase + lr) * DD + lc * 4;
    const float* Bp = CB + (size_t)(colBase + lr) * DD + lc * 4;

    float4 va0 = *(const float4*)(Ap);
    float4 va1 = *(const float4*)(Ap + 64 * DD);
    float4 vb0 = *(const float4*)(Bp);
    float4 vb1 = *(const float4*)(Bp + 64 * DD);

    As[0][lc*4+0][lr]    = va0.x; As[0][lc*4+1][lr]    = va0.y;
    As[0][lc*4+2][lr]    = va0.z; As[0][lc*4+3][lr]    = va0.w;
    As[0][lc*4+0][lr+64] = va1.x; As[0][lc*4+1][lr+64] = va1.y;
    As[0][lc*4+2][lr+64] = va1.z; As[0][lc*4+3][lr+64] = va1.w;
    Bs[0][lc*4+0][lr]    = vb0.x; Bs[0][lc*4+1][lr]    = vb0.y;
    Bs[0][lc*4+2][lr]    = vb0.z; Bs[0][lc*4+3][lr]    = vb0.w;
    Bs[0][lc*4+0][lr+64] = vb1.x; Bs[0][lc*4+1][lr+64] = vb1.y;
    Bs[0][lc*4+2][lr+64] = vb1.z; Bs[0][lc*4+3][lr+64] = vb1.w;
    __syncthreads();

    float acc[8][8];
    #pragma unroll
    for (int i = 0; i < 8; i++)
        #pragma unroll
        for (int j = 0; j < 8; j++) acc[i][j] = 0.f;

    const int NIT = DD / BK1;   // 32
    for (int kk = 0; kk < NIT; kk++) {
        const int cur = kk & 1, nxt = cur ^ 1;
        if (kk + 1 < NIT) {
            const float* Ap2 = Ap + (kk + 1) * BK1;
            const float* Bp2 = Bp + (kk + 1) * BK1;
            va0 = *(const float4*)(Ap2);
            va1 = *(const float4*)(Ap2 + 64 * DD);
            vb0 = *(const float4*)(Bp2);
            vb1 = *(const float4*)(Bp2 + 64 * DD);
        }
        #pragma unroll
        for (int p = 0; p < BK1; p++) {
            float a[8], b[8];
            *(float4*)(a)     = *(const float4*)&As[cur][p][ty * 8];
            *(float4*)(a + 4) = *(const float4*)&As[cur][p][ty * 8 + 4];
            *(float4*)(b)     = *(const float4*)&Bs[cur][p][tx * 8];
            *(float4*)(b + 4) = *(const float4*)&Bs[cur][p][tx * 8 + 4];
            #pragma unroll
            for (int i = 0; i < 8; i++)
                #pragma unroll
                for (int j = 0; j < 8; j++) acc[i][j] += a[i] * b[j];
        }
        if (kk + 1 < NIT) {
            As[nxt][lc*4+0][lr]    = va0.x; As[nxt][lc*4+1][lr]    = va0.y;
            As[nxt][lc*4+2][lr]    = va0.z; As[nxt][lc*4+3][lr]    = va0.w;
            As[nxt][lc*4+0][lr+64] = va1.x; As[nxt][lc*4+1][lr+64] = va1.y;
            As[nxt][lc*4+2][lr+64] = va1.z; As[nxt][lc*4+3][lr+64] = va1.w;
            Bs[nxt][lc*4+0][lr]    = vb0.x; Bs[nxt][lc*4+1][lr]    = vb0.y;
            Bs[nxt][lc*4+2][lr]    = vb0.z; Bs[nxt][lc*4+3][lr]    = vb0.w;
            Bs[nxt][lc*4+0][lr+64] = vb1.x; Bs[nxt][lc*4+1][lr+64] = vb1.y;
            Bs[nxt][lc*4+2][lr+64] = vb1.z; Bs[nxt][lc*4+3][lr+64] = vb1.w;
        }
        __syncthreads();
    }

    const float w = 0.5f / fmaxf(varq[0], 1e-10f);
    #pragma unroll
    for (int i = 0; i < 8; i++) {
        int n = rowBase + ty * 8 + i;
        float zzn = g_zz[n];
        float* dst = g_logits + (size_t)n * KC + colBase + tx * 8;
        #pragma unroll
        for (int j = 0; j < 8; j++) {
            int k = colBase + tx * 8 + j;
            dst[j] = w * (2.f * acc[i][j] - zzn - g_cc[k]);
        }
    }
}

// ---------------- mega kernel: per-row stats + colsum + sparse decode + diff ---
// Phase 1: online (m1,Z1,T1) over logits and (m2,Z2) over y=2(l+g), g inline.
// Phase 2: colsum atomics for p>1e-9; candidates with y-m2 > -18 into smem.
// Phase 3: z_dec row = sum E_k * CB[k]; fused (z - z_dec)^2 reduction.
#define CCAP 96
__global__ __launch_bounds__(256) void k_mega(const float* __restrict__ Z,
                                              const float* __restrict__ CB,
                                              float* __restrict__ out) {
    const int n = blockIdx.x;
    const float* __restrict__ lrow = g_logits + (size_t)n * KC;
    const unsigned ibase = (unsigned)n * KC;
    float m1 = -1e30f, Z1 = 0.f, T1 = 0.f, m2 = -1e30f, Z2 = 0.f;
    for (int k = threadIdx.x * 4; k < KC; k += 1024) {
        float4 l4 = *(const float4*)(lrow + k);
        #pragma unroll
        for (int q = 0; q < 4; q++) {
            float l = (q == 0) ? l4.x : (q == 1) ? l4.y : (q == 2) ? l4.z : l4.w;
            float g = gumbel_of(ibase + k + q);
            float y = 2.0f * (l + g);
            if (l > m1) {
                float d = m1 - l;
                float sc = __expf(d);
                T1 = sc * (T1 + d * Z1);
                Z1 *= sc;
                m1 = l;
            }
            float e = __expf(l - m1);
            Z1 += e; T1 += e * (l - m1);
            if (y > m2) { Z2 *= __expf(m2 - y); m2 = y; }
            Z2 += __expf(y - m2);
        }
    }
    __shared__ float sm1[256], sZ1[256], sT1[256], sm2[256], sZ2[256];
    __shared__ float s_fin[6];
    __shared__ int ccnt;
    __shared__ int   cidx[CCAP];
    __shared__ float cE[CCAP];
    int t = threadIdx.x;
    sm1[t] = m1; sZ1[t] = Z1; sT1[t] = T1; sm2[t] = m2; sZ2[t] = Z2;
    __syncthreads();
    for (int s = 128; s; s >>= 1) {
        if (t < s) {
            int o = t + s;
            float M = fmaxf(sm1[t], sm1[o]);
            float da = sm1[t] - M, db = sm1[o] - M;
            float ea = __expf(da), eb = __expf(db);
            sT1[t] = ea * (sT1[t] + da * sZ1[t]) + eb * (sT1[o] + db * sZ1[o]);
            sZ1[t] = ea * sZ1[t] + eb * sZ1[o];
            sm1[t] = M;
            float M2 = fmaxf(sm2[t], sm2[o]);
            sZ2[t] = sZ2[t] * __expf(sm2[t] - M2) + sZ2[o] * __expf(sm2[o] - M2);
            sm2[t] = M2;
        }
        __syncthreads();
    }
    if (t == 0) {
        float M = sm1[0], Zz = sZ1[0], T = sT1[0];
        atomicAdd(&g_scal[0], T / Zz - logf(Zz));     // row sum p*logp (exact)
        s_fin[0] = M;
        s_fin[1] = 1.f / Zz;
        s_fin[2] = M - 20.7233f + logf(Zz);           // p > 1e-9 cut on l
        s_fin[3] = sm2[0];
        s_fin[4] = 1.f / sZ2[0];
        s_fin[5] = 0.5f * (sm2[0] - 18.f) - 16.f;     // y can't reach m2-18 below this l
        ccnt = 0;
    }
    __syncthreads();
    const float m1v = s_fin[0], iZ1 = s_fin[1], lpc = s_fin[2];
    const float m2v = s_fin[3], iZ2 = s_fin[4], lyc = s_fin[5];
    for (int k = threadIdx.x * 4; k < KC; k += 1024) {
        float4 l4 = *(const float4*)(lrow + k);
        #pragma unroll
        for (int q = 0; q < 4; q++) {
            float l = (q == 0) ? l4.x : (q == 1) ? l4.y : (q == 2) ? l4.z : l4.w;
            if (l > lpc)
                atomicAdd(&g_colsum[k + q], __expf(l - m1v) * iZ1);
            if (l > lyc) {
                float g = gumbel_of(ibase + k + q);
                float y = 2.0f * (l + g);
                if (y - m2v > -18.f) {
                    int s = atomicAdd(&ccnt, 1);
                    if (s < CCAP) {
                        cidx[s] = k + q;
                        cE[s]   = __expf(y - m2v) * iZ2;
                    }
                }
            }
        }
    }
    __syncthreads();
    const int cnt = min(ccnt, CCAP);
    const int c0 = t * 2;
    float a0 = 0.f, a1 = 0.f;
    for (int j = 0; j < cnt; j++) {
        float e = cE[j];
        float2 cb = *(const float2*)(CB + (size_t)cidx[j] * DD + c0);
        a0 += e * cb.x;
        a1 += e * cb.y;
    }
    out[(size_t)n * DD + c0]     = a0;
    out[(size_t)n * DD + c0 + 1] = a1;
    float2 z2 = *(const float2*)(Z + (size_t)n * DD + c0);
    float d0 = z2.x - a0, d1 = z2.y - a1;
    sm1[t] = d0 * d0 + d1 * d1;
    __syncthreads();
    for (int s = 128; s; s >>= 1) {
        if (t < s) sm1[t] += sm1[t + s];
        __syncthreads();
    }
    if (t == 0) atomicAdd(&g_scal[1], sm1[0]);
}

// ---------------- finalize loss + perplexity ----------------
__global__ __launch_bounds__(256) void k_final(const float* __restrict__ varq,
                                               float* __restrict__ out, int out_size) {
    __shared__ float sh[256];
    float s = 0.f;
    for (int k = threadIdx.x; k < KC; k += 256) {
        float a = g_colsum[k] * (1.0f / (float)NR);
        s += a * logf(a + 1e-7f);
    }
    sh[threadIdx.x] = s;
    __syncthreads();
    for (int t = 128; t; t >>= 1) {
        if (threadIdx.x < t) sh[threadIdx.x] += sh[threadIdx.x + t];
        __syncthreads();
    }
    if (threadIdx.x == 0) {
        float w = 0.5f / fmaxf(varq[0], 1e-10f);
        float loss = g_scal[0] / (float)BSZ + w * g_scal[1] / (float)BSZ;
        float perp = expf(-sh[0]);
        if (out_size >= NR * DD + 2) {
            out[(size_t)NR * DD]     = loss;
            out[(size_t)NR * DD + 1] = perp;
        }
    }
}

// ---------------- launch ----------------
extern "C" void kernel_launch(void* const* d_in, const int* in_sizes, int n_in,
                              void* d_out, int out_size) {
    const float *Z = 0, *varq = 0, *CB = 0;
    for (int i = 0; i < n_in; i++) {
        if (in_sizes[i] == 1)            varq = (const float*)d_in[i];
        else if (in_sizes[i] == NR * DD) Z    = (const float*)d_in[i];
        else if (in_sizes[i] == KC * DD) CB   = (const float*)d_in[i];
    }
    float* out = (float*)d_out;

    k_zero<<<(KC + 255) / 256, 256>>>();
    k_sumsq<<<((NR + KC) * 32 + 255) / 256, 256>>>(Z, CB);
    k_gemm_logits<<<dim3(KC / BN1, NR / BM1), 256>>>(Z, CB, varq);
    k_mega<<<NR, 256>>>(Z, CB, out);
    k_final<<<1, 256>>>(varq, out, out_size);
}